// round 10
// baseline (speedup 1.0000x reference)
#include <cuda_runtime.h>
#include <cuda_bf16.h>
#include <cstdint>

// Problem dimensions (fixed by the dataset)
#define B_   32
#define T_   4096
#define H_   256
#define S_   256
#define BT_  (B_ * T_)          // 131072 rows
#define CHUNK 256
#define NCH   (T_ / CHUNK)      // 16 chunks

// ---------------------------------------------------------------------------
// Scratch (static __device__ arrays — allocation-free per harness rules)
// ---------------------------------------------------------------------------
__device__ __nv_bfloat16 g_xnh[(size_t)BT_ * H_];  // layernorm out hi
__device__ __nv_bfloat16 g_xnl[(size_t)BT_ * H_];  // layernorm out lo
__device__ float         g_u  [(size_t)BT_ * S_];  // u then fp32 states (scan)
__device__ __nv_bfloat16 g_sth[(size_t)BT_ * S_];  // corrected states hi
__device__ __nv_bfloat16 g_stl[(size_t)BT_ * S_];  // corrected states lo
__device__ __nv_bfloat16 g_mxh[(size_t)BT_ * H_];  // gelu(mixed) hi
__device__ __nv_bfloat16 g_mxl[(size_t)BT_ * H_];  // gelu(mixed) lo
__device__ float g_coeff [S_];
__device__ float g_coeffL[S_];
__device__ float g_e     [B_ * NCH * S_];
__device__ float g_carry [B_ * NCH * S_];
__device__ __nv_bfloat16 g_whi[3 * H_ * H_];       // weights hi (Win,Wsh,ow)
__device__ __nv_bfloat16 g_wlo[3 * H_ * H_];       // weights lo

// ---------------------------------------------------------------------------
// Math helpers
// ---------------------------------------------------------------------------
__device__ __forceinline__ float softplus_f(float v) {
    return fmaxf(v, 0.f) + log1pf(expf(-fabsf(v)));
}
__device__ __forceinline__ float gelu_tanh(float v) {
    float t = tanhf(0.7978845608028654f * (v + 0.044715f * v * v * v));
    return 0.5f * v * (1.0f + t);
}
__device__ __forceinline__ uint32_t smem_u32(const void* p) {
    uint32_t a;
    asm("{ .reg .u64 t; cvta.to.shared.u64 t, %1; cvt.u32.u64 %0, t; }"
        : "=r"(a) : "l"(p));
    return a;
}
__device__ __forceinline__ void splitw(float v, __nv_bfloat16& h, __nv_bfloat16& l) {
    h = __float2bfloat16_rn(v);
    l = __float2bfloat16_rn(v - __bfloat162float(h));
}

// ---------------------------------------------------------------------------
// mma.sync / ldmatrix / cp.async helpers (base sm_80+ PTX)
// ---------------------------------------------------------------------------
__device__ __forceinline__ void ldsm4(uint32_t* r, uint32_t a) {
    asm volatile("ldmatrix.sync.aligned.m8n8.x4.shared.b16 {%0,%1,%2,%3}, [%4];"
                 : "=r"(r[0]), "=r"(r[1]), "=r"(r[2]), "=r"(r[3]) : "r"(a));
}
__device__ __forceinline__ void mma16816(float* c, const uint32_t* a,
                                         uint32_t b0, uint32_t b1) {
    asm volatile(
        "mma.sync.aligned.m16n8k16.row.col.f32.bf16.bf16.f32 "
        "{%0,%1,%2,%3}, {%4,%5,%6,%7}, {%8,%9}, {%0,%1,%2,%3};"
        : "+f"(c[0]), "+f"(c[1]), "+f"(c[2]), "+f"(c[3])
        : "r"(a[0]), "r"(a[1]), "r"(a[2]), "r"(a[3]), "r"(b0), "r"(b1));
}
__device__ __forceinline__ void cpa16(uint32_t dst, const void* src) {
    asm volatile("cp.async.cg.shared.global [%0], [%1], 16;"
                 :: "r"(dst), "l"(src));
}
__device__ __forceinline__ void cpa_commit() {
    asm volatile("cp.async.commit_group;");
}
__device__ __forceinline__ void cpa_wait1() {
    asm volatile("cp.async.wait_group 1;");
}

// ---------------------------------------------------------------------------
// K0: recurrence coefficients
// ---------------------------------------------------------------------------
__global__ void k_coeff(const float* __restrict__ a_diag,
                        const float* __restrict__ g_diag,
                        const float* __restrict__ dt) {
    int s = threadIdx.x;
    float dts   = softplus_f(dt[s]) + 1e-4f;
    float omega = a_diag[s] * dts;
    float dec   = expf(-softplus_f(g_diag[s]) * dts);
    dec *= dec;
    float c = dec * cosf(omega);
    g_coeff[s] = c;
    float cl = c;
    #pragma unroll
    for (int i = 0; i < 8; i++) cl *= cl;   // c^256
    g_coeffL[s] = cl;
}

// ---------------------------------------------------------------------------
// K0b: pre-split the three weight matrices into bf16 hi/lo
// ---------------------------------------------------------------------------
__global__ void k_wsplit(const float* __restrict__ W0,
                         const float* __restrict__ W1,
                         const float* __restrict__ W2) {
    int id = blockIdx.x * 256 + threadIdx.x;      // grid 768
    int w = id >> 16, e = id & 65535;
    const float* src = (w == 0) ? W0 : (w == 1) ? W1 : W2;
    float v = src[e];
    __nv_bfloat16 h, l;
    splitw(v, h, l);
    g_whi[id] = h;
    g_wlo[id] = l;
}

// ---------------------------------------------------------------------------
// K1: LayerNorm per row -> bf16 hi/lo pair output
// ---------------------------------------------------------------------------
__global__ void k_ln(const float* __restrict__ x,
                     const float* __restrict__ w,
                     const float* __restrict__ b) {
    int row  = blockIdx.x * 8 + (threadIdx.x >> 5);
    int lane = threadIdx.x & 31;
    const float* xr = x + (size_t)row * H_;
    float v[8];
    float sum = 0.f;
    #pragma unroll
    for (int i = 0; i < 8; i++) { v[i] = xr[lane + 32 * i]; sum += v[i]; }
    #pragma unroll
    for (int o = 16; o; o >>= 1) sum += __shfl_xor_sync(0xffffffffu, sum, o);
    float mu = sum * (1.f / H_);
    float vs = 0.f;
    #pragma unroll
    for (int i = 0; i < 8; i++) { float d = v[i] - mu; vs += d * d; }
    #pragma unroll
    for (int o = 16; o; o >>= 1) vs += __shfl_xor_sync(0xffffffffu, vs, o);
    float rstd = rsqrtf(vs * (1.f / H_) + 1e-5f);
    size_t base = (size_t)row * H_;
    #pragma unroll
    for (int i = 0; i < 8; i++) {
        int col = lane + 32 * i;
        float xv = (v[i] - mu) * rstd * w[col] + b[col];
        __nv_bfloat16 h, l;
        splitw(xv, h, l);
        g_xnh[base + col] = h;
        g_xnl[base + col] = l;
    }
}

// ---------------------------------------------------------------------------
// bf16-split NT GEMM via mma.sync + 3-stage cp.async pipeline.
// C[m,n] = sum_k (Ah+Al)[m,k] * (Wh+Wl)[n,k]  via hh + hl + lh.
// BM=128, BN=256, BK=32, 512 threads (16 warps, 2m x 8n, warp tile 64x32).
// EPI 0: Cf = acc                         (u, fp32 for scan)
// EPI 1: split(gelu(acc + vec[n]*(math+matl)[m,n])) -> Ch,Cl
// EPI 2: Cf = matf[m,n] + acc + vec[n]    (y)
// ---------------------------------------------------------------------------
#define ROWB 80
#define SM_AH 0
#define SM_AL 10240
#define SM_BH 20480
#define SM_BL 40960
#define STG   61440
#define SM_TOT (3 * STG)        // 184320 bytes

template <int EPI>
__global__ void __launch_bounds__(512)
k_gemm_mma(const __nv_bfloat16* __restrict__ Ah,
           const __nv_bfloat16* __restrict__ Al,
           const __nv_bfloat16* __restrict__ Wh,
           const __nv_bfloat16* __restrict__ Wl,
           float* __restrict__ Cf,
           __nv_bfloat16* __restrict__ Ch,
           __nv_bfloat16* __restrict__ Cl,
           const float* __restrict__ vec,
           const float* __restrict__ matf,
           const __nv_bfloat16* __restrict__ math_,
           const __nv_bfloat16* __restrict__ matl_) {
    extern __shared__ __align__(128) char sm[];
    uint32_t sb = smem_u32(sm);
    int tid = threadIdx.x, lane = tid & 31, wid = tid >> 5;
    int wm = wid >> 3, wn = wid & 7;        // 2 x 8 warp grid
    size_t mBase = (size_t)blockIdx.x * 128;
    const __nv_bfloat16* Abh = Ah + mBase * 256;
    const __nv_bfloat16* Abl = Al + mBase * 256;

    // per-thread load slots (6 x 16B cp.async per stage)
    int arow = tid >> 2, ac = tid & 3;          // A: 128 rows x 4 chunks
    int brow0 = tid >> 2, brow1 = (tid + 512) >> 2;  // B: 256 rows x 4 chunks

    // prologue: stages 0,1 (chunks 0,1)
    #pragma unroll
    for (int s = 0; s < 2; s++) {
        uint32_t st = sb + s * STG;
        int kt = s * 32;
        uint32_t aoff = arow * ROWB + ac * 16;
        cpa16(st + SM_AH + aoff, Abh + (size_t)arow * 256 + kt + ac * 8);
        cpa16(st + SM_AL + aoff, Abl + (size_t)arow * 256 + kt + ac * 8);
        uint32_t b0 = brow0 * ROWB + ac * 16;
        uint32_t b1 = brow1 * ROWB + ac * 16;
        cpa16(st + SM_BH + b0, Wh + brow0 * 256 + kt + ac * 8);
        cpa16(st + SM_BH + b1, Wh + brow1 * 256 + kt + ac * 8);
        cpa16(st + SM_BL + b0, Wl + brow0 * 256 + kt + ac * 8);
        cpa16(st + SM_BL + b1, Wl + brow1 * 256 + kt + ac * 8);
        cpa_commit();
    }

    float acc[4][4][4];
    #pragma unroll
    for (int a = 0; a < 4; a++)
        #pragma unroll
        for (int b = 0; b < 4; b++)
            #pragma unroll
            for (int c = 0; c < 4; c++) acc[a][b][c] = 0.f;

    uint32_t aBase = sb + SM_AH + (wm * 64 + (lane & 15)) * ROWB + ((lane >> 4) << 4);
    uint32_t bBase = sb + SM_BH + (wn * 32 + (lane & 15)) * ROWB + ((lane >> 4) << 4);

    for (int ch = 0; ch < 8; ch++) {
        cpa_wait1();
        __syncthreads();

        // issue loads for chunk ch+2 into stage (ch+2)%3; always commit
        if (ch + 2 < 8) {
            uint32_t st = sb + ((ch + 2) % 3) * STG;
            int kt = (ch + 2) * 32;
            uint32_t aoff = arow * ROWB + ac * 16;
            cpa16(st + SM_AH + aoff, Abh + (size_t)arow * 256 + kt + ac * 8);
            cpa16(st + SM_AL + aoff, Abl + (size_t)arow * 256 + kt + ac * 8);
            uint32_t b0 = brow0 * ROWB + ac * 16;
            uint32_t b1 = brow1 * ROWB + ac * 16;
            cpa16(st + SM_BH + b0, Wh + brow0 * 256 + kt + ac * 8);
            cpa16(st + SM_BH + b1, Wh + brow1 * 256 + kt + ac * 8);
            cpa16(st + SM_BL + b0, Wl + brow0 * 256 + kt + ac * 8);
            cpa16(st + SM_BL + b1, Wl + brow1 * 256 + kt + ac * 8);
        }
        cpa_commit();

        uint32_t stg = (uint32_t)((ch % 3) * STG);
        uint32_t aAddr = aBase + stg, bAddr = bBase + stg;
        #pragma unroll
        for (int ks = 0; ks < 2; ks++) {
            uint32_t kO = ks * 32;
            uint32_t bh[8], bl[8];
            ldsm4(bh,     bAddr + kO);
            ldsm4(bh + 4, bAddr + 16 * ROWB + kO);
            ldsm4(bl,     bAddr + (SM_BL - SM_BH) + kO);
            ldsm4(bl + 4, bAddr + (SM_BL - SM_BH) + 16 * ROWB + kO);
            #pragma unroll
            for (int mt = 0; mt < 4; mt++) {
                uint32_t ah[4], al[4];
                ldsm4(ah, aAddr + mt * 16 * ROWB + kO);
                ldsm4(al, aAddr + (SM_AL - SM_AH) + mt * 16 * ROWB + kO);
                #pragma unroll
                for (int nt = 0; nt < 4; nt++) {
                    int g = (nt >> 1) * 4, s2 = nt & 1;
                    mma16816(acc[mt][nt], ah, bh[g + s2], bh[g + s2 + 2]);
                    mma16816(acc[mt][nt], ah, bl[g + s2], bl[g + s2 + 2]);
                    mma16816(acc[mt][nt], al, bh[g + s2], bh[g + s2 + 2]);
                }
            }
        }
    }

    // Epilogue: c0,c1 at (m, n..n+1); c2,c3 at (m+8, n..n+1)
    #pragma unroll
    for (int mt = 0; mt < 4; mt++) {
        size_t m0 = mBase + (size_t)(wm * 64 + mt * 16 + (lane >> 2));
        #pragma unroll
        for (int nt = 0; nt < 4; nt++) {
            int n = wn * 32 + nt * 8 + (lane & 3) * 2;
            #pragma unroll
            for (int h = 0; h < 2; h++) {
                size_t m = m0 + h * 8;
                size_t idx = m * 256 + (size_t)n;
                float v0 = acc[mt][nt][h * 2], v1 = acc[mt][nt][h * 2 + 1];
                if (EPI == 0) {
                    *(float2*)(Cf + idx) = make_float2(v0, v1);
                } else if (EPI == 1) {
                    float x0 = __bfloat162float(math_[idx]) +
                               __bfloat162float(matl_[idx]);
                    float x1 = __bfloat162float(math_[idx + 1]) +
                               __bfloat162float(matl_[idx + 1]);
                    float gl0 = gelu_tanh(v0 + vec[n] * x0);
                    float gl1 = gelu_tanh(v1 + vec[n + 1] * x1);
                    __nv_bfloat16 h0, l0, h1, l1;
                    splitw(gl0, h0, l0);
                    splitw(gl1, h1, l1);
                    *(__nv_bfloat162*)(Ch + idx) = __nv_bfloat162(h0, h1);
                    *(__nv_bfloat162*)(Cl + idx) = __nv_bfloat162(l0, l1);
                } else {
                    float o0 = matf[idx]     + v0 + vec[n];
                    float o1 = matf[idx + 1] + v1 + vec[n + 1];
                    *(float2*)(Cf + idx) = make_float2(o0, o1);
                }
            }
        }
    }
}

// ---------------------------------------------------------------------------
// Scan phase 1: chunk-local scan (zero initial), in-place on g_u.
// ---------------------------------------------------------------------------
__global__ void k_scan1() {
    int s  = threadIdx.x;
    int ch = blockIdx.x;
    int b  = blockIdx.y;
    float c = g_coeff[s];
    size_t base = ((size_t)b * T_ + (size_t)ch * CHUNK) * S_ + s;
    float st = 0.f;
    #pragma unroll 8
    for (int t = 0; t < CHUNK; t++) {
        size_t idx = base + (size_t)t * S_;
        st = fmaf(c, st, g_u[idx]);
        g_u[idx] = st;
    }
    g_e[(b * NCH + ch) * S_ + s] = st;
}

// ---------------------------------------------------------------------------
// Scan phase 2: carry scan across chunks; writes carry_in + final_state.
// ---------------------------------------------------------------------------
__global__ void k_scan2(const float* __restrict__ state0, float* fs_out) {
    int s = threadIdx.x;
    int b = blockIdx.x;
    float cl  = g_coeffL[s];
    float Sin = state0[b * S_ + s];
    #pragma unroll
    for (int ch = 0; ch < NCH; ch++) {
        int e = (b * NCH + ch) * S_ + s;
        g_carry[e] = Sin;
        Sin = fmaf(cl, Sin, g_e[e]);
    }
    if (fs_out) fs_out[b * S_ + s] = Sin;
}

// ---------------------------------------------------------------------------
// Scan phase 3: correction + bf16 hi/lo split of the corrected states.
// ---------------------------------------------------------------------------
__global__ void k_scan3() {
    int s  = threadIdx.x;
    int ch = blockIdx.x;
    int b  = blockIdx.y;
    float c     = g_coeff[s];
    float carry = g_carry[(b * NCH + ch) * S_ + s];
    float cp = c;
    size_t base = ((size_t)b * T_ + (size_t)ch * CHUNK) * S_ + s;
    #pragma unroll 8
    for (int t = 0; t < CHUNK; t++) {
        size_t idx = base + (size_t)t * S_;
        float v = fmaf(cp, carry, g_u[idx]);
        __nv_bfloat16 h, l;
        splitw(v, h, l);
        g_sth[idx] = h;
        g_stl[idx] = l;
        cp *= c;
    }
}

// ---------------------------------------------------------------------------
// Launch
// ---------------------------------------------------------------------------
extern "C" void kernel_launch(void* const* d_in, const int* in_sizes, int n_in,
                              void* d_out, int out_size) {
    const float* x      = (const float*)d_in[0];
    const float* state0 = (const float*)d_in[1];
    const float* Win    = (const float*)d_in[2];   // [S,H]
    const float* Wsh    = (const float*)d_in[3];   // [H,S]
    const float* direct = (const float*)d_in[4];   // [H]
    const float* a_diag = (const float*)d_in[5];
    const float* g_diag = (const float*)d_in[6];
    const float* dt     = (const float*)d_in[7];
    const float* nw     = (const float*)d_in[8];
    const float* nb     = (const float*)d_in[9];
    const float* ow     = (const float*)d_in[10];  // [H,H]
    const float* ob     = (const float*)d_in[11];
    float* out = (float*)d_out;

    float *u;
    __nv_bfloat16 *xnh, *xnl, *sth, *stl, *mxh, *mxl, *wh, *wl;
    cudaGetSymbolAddress((void**)&u,   g_u);
    cudaGetSymbolAddress((void**)&xnh, g_xnh);
    cudaGetSymbolAddress((void**)&xnl, g_xnl);
    cudaGetSymbolAddress((void**)&sth, g_sth);
    cudaGetSymbolAddress((void**)&stl, g_stl);
    cudaGetSymbolAddress((void**)&mxh, g_mxh);
    cudaGetSymbolAddress((void**)&mxl, g_mxl);
    cudaGetSymbolAddress((void**)&wh,  g_whi);
    cudaGetSymbolAddress((void**)&wl,  g_wlo);

    cudaFuncSetAttribute(k_gemm_mma<0>, cudaFuncAttributeMaxDynamicSharedMemorySize, SM_TOT);
    cudaFuncSetAttribute(k_gemm_mma<1>, cudaFuncAttributeMaxDynamicSharedMemorySize, SM_TOT);
    cudaFuncSetAttribute(k_gemm_mma<2>, cudaFuncAttributeMaxDynamicSharedMemorySize, SM_TOT);

    k_coeff<<<1, S_>>>(a_diag, g_diag, dt);
    k_wsplit<<<768, 256>>>(Win, Wsh, ow);
    k_ln<<<BT_ / 8, 256>>>(x, nw, nb);

    // u = xn @ Win^T
    k_gemm_mma<0><<<BT_ / 128, 512, SM_TOT>>>(
        xnh, xnl, wh, wl, u, nullptr, nullptr, nullptr, nullptr, nullptr, nullptr);

    // diagonal linear recurrence (chunked parallel scan)
    k_scan1<<<dim3(NCH, B_), 256>>>();
    float* fs_out = ((size_t)out_size >= (size_t)BT_ * H_ + (size_t)B_ * S_)
                        ? out + (size_t)BT_ * H_ : nullptr;
    k_scan2<<<B_, 256>>>(state0, fs_out);
    k_scan3<<<dim3(NCH, B_), 256>>>();

    // mixed = gelu(states @ Wsh^T + direct * xn)  -> bf16 hi/lo
    k_gemm_mma<1><<<BT_ / 128, 512, SM_TOT>>>(
        sth, stl, wh + 65536, wl + 65536, nullptr, mxh, mxl, direct,
        nullptr, xnh, xnl);

    // y = x + mixed @ ow^T + ob
    k_gemm_mma<2><<<BT_ / 128, 512, SM_TOT>>>(
        mxh, mxl, wh + 131072, wl + 131072, out, nullptr, nullptr, ob,
        x, nullptr, nullptr);
}

// round 11
// speedup vs baseline: 1.1736x; 1.1736x over previous
#include <cuda_runtime.h>
#include <cuda_bf16.h>
#include <cstdint>

// Problem dimensions (fixed by the dataset)
#define B_   32
#define T_   4096
#define H_   256
#define S_   256
#define BT_  (B_ * T_)          // 131072 rows
#define CHUNK 256
#define NCH   (T_ / CHUNK)      // 16 chunks

// ---------------------------------------------------------------------------
// Scratch (static __device__ arrays — allocation-free per harness rules)
// ---------------------------------------------------------------------------
__device__ float g_xn[(size_t)BT_ * H_];   // layernormed x        [BT,H]
__device__ float g_u [(size_t)BT_ * S_];   // u, then states (in-place scan) [BT,S]
__device__ float g_mx[(size_t)BT_ * H_];   // gelu(mixed)          [BT,H]
__device__ float g_coeff [S_];
__device__ float g_coeffL[S_];
__device__ float g_e     [B_ * NCH * S_];
__device__ float g_carry [B_ * NCH * S_];
__device__ __nv_bfloat16 g_whi[3 * H_ * H_];  // weights hi (Win,Wsh,ow)
__device__ __nv_bfloat16 g_wlo[3 * H_ * H_];  // weights lo

// ---------------------------------------------------------------------------
// Math helpers
// ---------------------------------------------------------------------------
__device__ __forceinline__ float softplus_f(float v) {
    return fmaxf(v, 0.f) + log1pf(expf(-fabsf(v)));
}
__device__ __forceinline__ float gelu_tanh(float v) {
    float t = tanhf(0.7978845608028654f * (v + 0.044715f * v * v * v));
    return 0.5f * v * (1.0f + t);
}
__device__ __forceinline__ uint32_t smem_u32(const void* p) {
    uint32_t a;
    asm("{ .reg .u64 t; cvta.to.shared.u64 t, %1; cvt.u32.u64 %0, t; }"
        : "=r"(a) : "l"(p));
    return a;
}

// ---------------------------------------------------------------------------
// mma.sync / ldmatrix / cp.async helpers (base sm_80+ PTX)
// ---------------------------------------------------------------------------
__device__ __forceinline__ void ldsm4(uint32_t* r, uint32_t a) {
    asm volatile("ldmatrix.sync.aligned.m8n8.x4.shared.b16 {%0,%1,%2,%3}, [%4];"
                 : "=r"(r[0]), "=r"(r[1]), "=r"(r[2]), "=r"(r[3]) : "r"(a));
}
__device__ __forceinline__ void mma16816(float* c, const uint32_t* a,
                                         uint32_t b0, uint32_t b1) {
    asm volatile(
        "mma.sync.aligned.m16n8k16.row.col.f32.bf16.bf16.f32 "
        "{%0,%1,%2,%3}, {%4,%5,%6,%7}, {%8,%9}, {%0,%1,%2,%3};"
        : "+f"(c[0]), "+f"(c[1]), "+f"(c[2]), "+f"(c[3])
        : "r"(a[0]), "r"(a[1]), "r"(a[2]), "r"(a[3]), "r"(b0), "r"(b1));
}
__device__ __forceinline__ void cpa16(uint32_t dst, const void* src) {
    asm volatile("cp.async.cg.shared.global [%0], [%1], 16;"
                 :: "r"(dst), "l"(src));
}
__device__ __forceinline__ void cpa_commit() {
    asm volatile("cp.async.commit_group;");
}
__device__ __forceinline__ void cpa_wait1() {
    asm volatile("cp.async.wait_group 1;");
}

// Convert float4 -> bf16 hi/lo pairs and store 8B each
__device__ __forceinline__ void split_store(float4 v, char* ph, char* pl) {
    __nv_bfloat162 h0 = __floats2bfloat162_rn(v.x, v.y);
    __nv_bfloat162 h1 = __floats2bfloat162_rn(v.z, v.w);
    float rx = v.x - __bfloat162float(h0.x);
    float ry = v.y - __bfloat162float(h0.y);
    float rz = v.z - __bfloat162float(h1.x);
    float rw = v.w - __bfloat162float(h1.y);
    __nv_bfloat162 l0 = __floats2bfloat162_rn(rx, ry);
    __nv_bfloat162 l1 = __floats2bfloat162_rn(rz, rw);
    *(uint2*)ph = make_uint2(*(uint32_t*)&h0, *(uint32_t*)&h1);
    *(uint2*)pl = make_uint2(*(uint32_t*)&l0, *(uint32_t*)&l1);
}

// ---------------------------------------------------------------------------
// K0: recurrence coefficients
// ---------------------------------------------------------------------------
__global__ void k_coeff(const float* __restrict__ a_diag,
                        const float* __restrict__ g_diag,
                        const float* __restrict__ dt) {
    int s = threadIdx.x;
    float dts   = softplus_f(dt[s]) + 1e-4f;
    float omega = a_diag[s] * dts;
    float dec   = expf(-softplus_f(g_diag[s]) * dts);
    dec *= dec;
    float c = dec * cosf(omega);
    g_coeff[s] = c;
    float cl = c;
    #pragma unroll
    for (int i = 0; i < 8; i++) cl *= cl;   // c^256
    g_coeffL[s] = cl;
}

// ---------------------------------------------------------------------------
// K0b: pre-split the three weight matrices into bf16 hi/lo
// ---------------------------------------------------------------------------
__global__ void k_wsplit(const float* __restrict__ W0,
                         const float* __restrict__ W1,
                         const float* __restrict__ W2) {
    int id = blockIdx.x * 256 + threadIdx.x;      // grid 768
    int w = id >> 16, e = id & 65535;
    const float* src = (w == 0) ? W0 : (w == 1) ? W1 : W2;
    float v = src[e];
    __nv_bfloat16 h = __float2bfloat16_rn(v);
    g_whi[id] = h;
    g_wlo[id] = __float2bfloat16_rn(v - __bfloat162float(h));
}

// ---------------------------------------------------------------------------
// K1: LayerNorm per row (warp per row, 8 rows per block)
// ---------------------------------------------------------------------------
__global__ void k_ln(const float* __restrict__ x,
                     const float* __restrict__ w,
                     const float* __restrict__ b) {
    int row  = blockIdx.x * 8 + (threadIdx.x >> 5);
    int lane = threadIdx.x & 31;
    const float* xr = x + (size_t)row * H_;
    float v[8];
    float sum = 0.f;
    #pragma unroll
    for (int i = 0; i < 8; i++) { v[i] = xr[lane + 32 * i]; sum += v[i]; }
    #pragma unroll
    for (int o = 16; o; o >>= 1) sum += __shfl_xor_sync(0xffffffffu, sum, o);
    float mu = sum * (1.f / H_);
    float vs = 0.f;
    #pragma unroll
    for (int i = 0; i < 8; i++) { float d = v[i] - mu; vs += d * d; }
    #pragma unroll
    for (int o = 16; o; o >>= 1) vs += __shfl_xor_sync(0xffffffffu, vs, o);
    float rstd = rsqrtf(vs * (1.f / H_) + 1e-5f);
    float* outr = g_xn + (size_t)row * H_;
    #pragma unroll
    for (int i = 0; i < 8; i++) {
        int col = lane + 32 * i;
        outr[col] = (v[i] - mu) * rstd * w[col] + b[col];
    }
}

// ---------------------------------------------------------------------------
// bf16-split NT GEMM via mma.sync:  C[m,n] = sum_k A[m,k] * W[n,k]
// BM=128, BN=128 (grid.y=2), BK=32, 256 threads (8 warps 2m x 4n, tile 64x32).
// A fp32, split on the fly into double-buffered smem; W pre-split bf16,
// loaded via 3-stage cp.async. fp32 recovered as hh + hl + lh.
// 2 CTAs/SM (smem 100KB, regs capped 128).
// EPI 0: C = acc                              (u)
// EPI 1: C = gelu(acc + p0[n]*p1[m,n])        (mixed)
// EPI 2: C = p0[m,n] + acc + p1[n]            (y)
// ---------------------------------------------------------------------------
#define ROWB 80
#define AHALF 10240             // 128 rows * 80B
#define ASTG  20480             // hi + lo
#define BSTG  20480
#define BBASE 40960             // after 2 A stages
#define SM_TOT (BBASE + 3 * BSTG)   // 102400 bytes

template <int EPI>
__global__ void __launch_bounds__(256, 2)
k_gemm_mma(const float* __restrict__ A,
           const __nv_bfloat16* __restrict__ Wh,
           const __nv_bfloat16* __restrict__ Wl,
           float* __restrict__ C,
           const float* __restrict__ p0,
           const float* __restrict__ p1) {
    extern __shared__ __align__(128) char sm[];
    uint32_t sb = smem_u32(sm);
    int tid = threadIdx.x, lane = tid & 31, wid = tid >> 5;
    int wm = wid >> 2, wn = wid & 3;        // 2 x 4 warp grid
    size_t mBase = (size_t)blockIdx.x * 128;
    int    nBase = blockIdx.y * 128;
    const float* Ab = A + mBase * 256;
    const __nv_bfloat16* Wbh = Wh + (size_t)nBase * 256;
    const __nv_bfloat16* Wbl = Wl + (size_t)nBase * 256;

    // A: 4 float4 per thread per chunk (128 rows x 32 cols fp32)
    // B: 2 hi + 2 lo cp.async-16B per thread per chunk (128 rows x 32 cols bf16)
    float4 ra[4];
    #pragma unroll
    for (int i = 0; i < 4; i++) {
        int idx = tid + 256 * i;
        ra[i] = *(const float4*)(Ab + (size_t)(idx >> 3) * 256 + ((idx & 7) << 2));
    }
    #pragma unroll
    for (int i = 0; i < 4; i++) {           // A chunk0 -> stage 0
        int idx = tid + 256 * i;
        int off = (idx >> 3) * ROWB + (idx & 7) * 8;
        split_store(ra[i], sm + off, sm + AHALF + off);
    }
    #pragma unroll
    for (int s = 0; s < 2; s++) {           // B chunks 0,1 -> stages 0,1
        uint32_t st = sb + BBASE + s * BSTG;
        int kt = s * 32;
        #pragma unroll
        for (int i = 0; i < 2; i++) {
            int slot = tid + 256 * i;
            int r = slot >> 2, q = slot & 3;
            uint32_t doff = r * ROWB + q * 16;
            cpa16(st + doff,         Wbh + (size_t)r * 256 + kt + q * 8);
            cpa16(st + AHALF + doff, Wbl + (size_t)r * 256 + kt + q * 8);
        }
        cpa_commit();
    }
    #pragma unroll
    for (int i = 0; i < 4; i++) {           // A chunk1 -> regs
        int idx = tid + 256 * i;
        ra[i] = *(const float4*)(Ab + (size_t)(idx >> 3) * 256 + 32 + ((idx & 7) << 2));
    }

    float acc[4][4][4];
    #pragma unroll
    for (int a = 0; a < 4; a++)
        #pragma unroll
        for (int b = 0; b < 4; b++)
            #pragma unroll
            for (int c = 0; c < 4; c++) acc[a][b][c] = 0.f;

    uint32_t aW = (uint32_t)((wm * 64 + (lane & 15)) * ROWB + ((lane >> 4) << 4));
    uint32_t bW = (uint32_t)((wn * 32 + (lane & 15)) * ROWB + ((lane >> 4) << 4));

    for (int ch = 0; ch < 8; ch++) {
        cpa_wait1();
        __syncthreads();

        if (ch + 2 < 8) {                   // B chunk ch+2 -> stage (ch+2)%3
            uint32_t st = sb + BBASE + ((ch + 2) % 3) * BSTG;
            int kt = (ch + 2) * 32;
            #pragma unroll
            for (int i = 0; i < 2; i++) {
                int slot = tid + 256 * i;
                int r = slot >> 2, q = slot & 3;
                uint32_t doff = r * ROWB + q * 16;
                cpa16(st + doff,         Wbh + (size_t)r * 256 + kt + q * 8);
                cpa16(st + AHALF + doff, Wbl + (size_t)r * 256 + kt + q * 8);
            }
        }
        cpa_commit();

        uint32_t aS = sb + (uint32_t)((ch & 1) * ASTG);
        uint32_t bS = sb + BBASE + (uint32_t)((ch % 3) * BSTG);
        uint32_t aAddr = aS + aW, bAddr = bS + bW;

        #pragma unroll
        for (int ks = 0; ks < 2; ks++) {
            uint32_t kO = ks * 32;
            uint32_t bh[8], bl[8];
            ldsm4(bh,     bAddr + kO);
            ldsm4(bh + 4, bAddr + 16 * ROWB + kO);
            ldsm4(bl,     bAddr + AHALF + kO);
            ldsm4(bl + 4, bAddr + AHALF + 16 * ROWB + kO);
            #pragma unroll
            for (int mt = 0; mt < 4; mt++) {
                uint32_t ah[4], al[4];
                ldsm4(ah, aAddr + mt * 16 * ROWB + kO);
                ldsm4(al, aAddr + AHALF + mt * 16 * ROWB + kO);
                #pragma unroll
                for (int nt = 0; nt < 4; nt++) {
                    int g = (nt >> 1) * 4, s2 = nt & 1;
                    mma16816(acc[mt][nt], ah, bh[g + s2], bh[g + s2 + 2]);
                    mma16816(acc[mt][nt], ah, bl[g + s2], bl[g + s2 + 2]);
                    mma16816(acc[mt][nt], al, bh[g + s2], bh[g + s2 + 2]);
                }
            }
            // Between ks0 and ks1: stage A(ch+1) into the other A buffer
            // (no barrier needed — different buffer, covered by next sync),
            // then prefetch A(ch+2) into registers.
            if (ks == 0 && ch < 7) {
                uint32_t aD = (uint32_t)(((ch + 1) & 1) * ASTG);
                #pragma unroll
                for (int i = 0; i < 4; i++) {
                    int idx = tid + 256 * i;
                    int off = (idx >> 3) * ROWB + (idx & 7) * 8;
                    split_store(ra[i], sm + aD + off, sm + aD + AHALF + off);
                }
                if (ch + 2 < 8) {
                    int kt = (ch + 2) * 32;
                    #pragma unroll
                    for (int i = 0; i < 4; i++) {
                        int idx = tid + 256 * i;
                        ra[i] = *(const float4*)(Ab + (size_t)(idx >> 3) * 256 + kt + ((idx & 7) << 2));
                    }
                }
            }
        }
    }

    // Epilogue: c0,c1 at (m, n..n+1); c2,c3 at (m+8, n..n+1)
    #pragma unroll
    for (int mt = 0; mt < 4; mt++) {
        size_t m0 = mBase + (size_t)(wm * 64 + mt * 16 + (lane >> 2));
        #pragma unroll
        for (int nt = 0; nt < 4; nt++) {
            int n = nBase + wn * 32 + nt * 8 + (lane & 3) * 2;
            #pragma unroll
            for (int h = 0; h < 2; h++) {
                size_t m = m0 + h * 8;
                size_t idx = m * 256 + (size_t)n;
                float v0 = acc[mt][nt][h * 2], v1 = acc[mt][nt][h * 2 + 1];
                float2 o;
                if (EPI == 0) {
                    o = make_float2(v0, v1);
                } else if (EPI == 1) {
                    o.x = gelu_tanh(v0 + p0[n]     * p1[idx]);
                    o.y = gelu_tanh(v1 + p0[n + 1] * p1[idx + 1]);
                } else {
                    o.x = p0[idx]     + v0 + p1[n];
                    o.y = p0[idx + 1] + v1 + p1[n + 1];
                }
                *(float2*)(C + idx) = o;
            }
        }
    }
}

// ---------------------------------------------------------------------------
// Scan phase 1: chunk-local scan (zero initial), in-place on g_u.
// ---------------------------------------------------------------------------
__global__ void k_scan1() {
    int s  = threadIdx.x;
    int ch = blockIdx.x;
    int b  = blockIdx.y;
    float c = g_coeff[s];
    size_t base = ((size_t)b * T_ + (size_t)ch * CHUNK) * S_ + s;
    float st = 0.f;
    #pragma unroll 8
    for (int t = 0; t < CHUNK; t++) {
        size_t idx = base + (size_t)t * S_;
        st = fmaf(c, st, g_u[idx]);
        g_u[idx] = st;
    }
    g_e[(b * NCH + ch) * S_ + s] = st;
}

// ---------------------------------------------------------------------------
// Scan phase 2: carry scan across chunks; writes carry_in + final_state.
// ---------------------------------------------------------------------------
__global__ void k_scan2(const float* __restrict__ state0, float* fs_out) {
    int s = threadIdx.x;
    int b = blockIdx.x;
    float cl  = g_coeffL[s];
    float Sin = state0[b * S_ + s];
    #pragma unroll
    for (int ch = 0; ch < NCH; ch++) {
        int e = (b * NCH + ch) * S_ + s;
        g_carry[e] = Sin;
        Sin = fmaf(cl, Sin, g_e[e]);
    }
    if (fs_out) fs_out[b * S_ + s] = Sin;
}

// ---------------------------------------------------------------------------
// Scan phase 3: correction  states[t] += coeff^(t+1) * carry_in
// ---------------------------------------------------------------------------
__global__ void k_scan3() {
    int s  = threadIdx.x;
    int ch = blockIdx.x;
    int b  = blockIdx.y;
    float c     = g_coeff[s];
    float carry = g_carry[(b * NCH + ch) * S_ + s];
    float cp = c;
    size_t base = ((size_t)b * T_ + (size_t)ch * CHUNK) * S_ + s;
    #pragma unroll 8
    for (int t = 0; t < CHUNK; t++) {
        size_t idx = base + (size_t)t * S_;
        g_u[idx] = fmaf(cp, carry, g_u[idx]);
        cp *= c;
    }
}

// ---------------------------------------------------------------------------
// Launch
// ---------------------------------------------------------------------------
extern "C" void kernel_launch(void* const* d_in, const int* in_sizes, int n_in,
                              void* d_out, int out_size) {
    const float* x      = (const float*)d_in[0];
    const float* state0 = (const float*)d_in[1];
    const float* Win    = (const float*)d_in[2];   // [S,H]
    const float* Wsh    = (const float*)d_in[3];   // [H,S]
    const float* direct = (const float*)d_in[4];   // [H]
    const float* a_diag = (const float*)d_in[5];
    const float* g_diag = (const float*)d_in[6];
    const float* dt     = (const float*)d_in[7];
    const float* nw     = (const float*)d_in[8];
    const float* nb     = (const float*)d_in[9];
    const float* ow     = (const float*)d_in[10];  // [H,H]
    const float* ob     = (const float*)d_in[11];
    float* out = (float*)d_out;

    float *xn, *u, *mx;
    __nv_bfloat16 *wh, *wl;
    cudaGetSymbolAddress((void**)&xn, g_xn);
    cudaGetSymbolAddress((void**)&u,  g_u);
    cudaGetSymbolAddress((void**)&mx, g_mx);
    cudaGetSymbolAddress((void**)&wh, g_whi);
    cudaGetSymbolAddress((void**)&wl, g_wlo);

    cudaFuncSetAttribute(k_gemm_mma<0>, cudaFuncAttributeMaxDynamicSharedMemorySize, SM_TOT);
    cudaFuncSetAttribute(k_gemm_mma<1>, cudaFuncAttributeMaxDynamicSharedMemorySize, SM_TOT);
    cudaFuncSetAttribute(k_gemm_mma<2>, cudaFuncAttributeMaxDynamicSharedMemorySize, SM_TOT);

    k_coeff<<<1, S_>>>(a_diag, g_diag, dt);
    k_wsplit<<<768, 256>>>(Win, Wsh, ow);
    k_ln<<<BT_ / 8, 256>>>(x, nw, nb);

    dim3 gg(BT_ / 128, 2);

    // u = xn @ Win^T
    k_gemm_mma<0><<<gg, 256, SM_TOT>>>(xn, wh, wl, u, nullptr, nullptr);

    // diagonal linear recurrence (chunked parallel scan)
    k_scan1<<<dim3(NCH, B_), 256>>>();
    float* fs_out = ((size_t)out_size >= (size_t)BT_ * H_ + (size_t)B_ * S_)
                        ? out + (size_t)BT_ * H_ : nullptr;
    k_scan2<<<B_, 256>>>(state0, fs_out);
    k_scan3<<<dim3(NCH, B_), 256>>>();

    // mixed = gelu(states @ Wsh^T + direct * xn)
    k_gemm_mma<1><<<gg, 256, SM_TOT>>>(u, wh + 65536, wl + 65536, mx, direct, xn);

    // y = x + mixed @ ow^T + ob
    k_gemm_mma<2><<<gg, 256, SM_TOT>>>(mx, wh + 131072, wl + 131072, out, x, ob);
}

// round 12
// speedup vs baseline: 1.1773x; 1.0032x over previous
#include <cuda_runtime.h>
#include <cuda_bf16.h>
#include <cstdint>

// Problem dimensions (fixed by the dataset)
#define B_   32
#define T_   4096
#define H_   256
#define S_   256
#define BT_  (B_ * T_)          // 131072 rows
#define CHUNK 256
#define NCH   (T_ / CHUNK)      // 16 chunks

// ---------------------------------------------------------------------------
// Scratch (static __device__ arrays — allocation-free per harness rules)
// ---------------------------------------------------------------------------
__device__ float g_xn[(size_t)BT_ * H_];   // layernormed x        [BT,H]
__device__ float g_u [(size_t)BT_ * S_];   // u, then states (in-place scan) [BT,S]
__device__ float g_mx[(size_t)BT_ * H_];   // gelu(mixed)          [BT,H]
__device__ float g_coeff [S_];
__device__ float g_coeffL[S_];
__device__ float g_e     [B_ * NCH * S_];
__device__ float g_carry [B_ * NCH * S_];
__device__ __nv_bfloat16 g_whi[3 * H_ * H_];  // weights hi (Win,Wsh,ow)
__device__ __nv_bfloat16 g_wlo[3 * H_ * H_];  // weights lo

// ---------------------------------------------------------------------------
// Math helpers
// ---------------------------------------------------------------------------
__device__ __forceinline__ float softplus_f(float v) {
    return fmaxf(v, 0.f) + log1pf(expf(-fabsf(v)));
}
__device__ __forceinline__ float gelu_tanh(float v) {
    float t = tanhf(0.7978845608028654f * (v + 0.044715f * v * v * v));
    return 0.5f * v * (1.0f + t);
}
__device__ __forceinline__ uint32_t smem_u32(const void* p) {
    uint32_t a;
    asm("{ .reg .u64 t; cvta.to.shared.u64 t, %1; cvt.u32.u64 %0, t; }"
        : "=r"(a) : "l"(p));
    return a;
}

// ---------------------------------------------------------------------------
// mma.sync / ldmatrix / cp.async helpers (base sm_80+ PTX)
// ---------------------------------------------------------------------------
__device__ __forceinline__ void ldsm4(uint32_t* r, uint32_t a) {
    asm volatile("ldmatrix.sync.aligned.m8n8.x4.shared.b16 {%0,%1,%2,%3}, [%4];"
                 : "=r"(r[0]), "=r"(r[1]), "=r"(r[2]), "=r"(r[3]) : "r"(a));
}
__device__ __forceinline__ void mma16816(float* c, const uint32_t* a,
                                         uint32_t b0, uint32_t b1) {
    asm volatile(
        "mma.sync.aligned.m16n8k16.row.col.f32.bf16.bf16.f32 "
        "{%0,%1,%2,%3}, {%4,%5,%6,%7}, {%8,%9}, {%0,%1,%2,%3};"
        : "+f"(c[0]), "+f"(c[1]), "+f"(c[2]), "+f"(c[3])
        : "r"(a[0]), "r"(a[1]), "r"(a[2]), "r"(a[3]), "r"(b0), "r"(b1));
}
__device__ __forceinline__ void cpa16(uint32_t dst, const void* src) {
    asm volatile("cp.async.cg.shared.global [%0], [%1], 16;"
                 :: "r"(dst), "l"(src));
}
__device__ __forceinline__ void cpa_commit() {
    asm volatile("cp.async.commit_group;");
}
__device__ __forceinline__ void cpa_wait1() {
    asm volatile("cp.async.wait_group 1;");
}

// Convert float4 -> bf16 hi/lo pairs and store 8B each
__device__ __forceinline__ void split_store(float4 v, char* ph, char* pl) {
    __nv_bfloat162 h0 = __floats2bfloat162_rn(v.x, v.y);
    __nv_bfloat162 h1 = __floats2bfloat162_rn(v.z, v.w);
    float rx = v.x - __bfloat162float(h0.x);
    float ry = v.y - __bfloat162float(h0.y);
    float rz = v.z - __bfloat162float(h1.x);
    float rw = v.w - __bfloat162float(h1.y);
    __nv_bfloat162 l0 = __floats2bfloat162_rn(rx, ry);
    __nv_bfloat162 l1 = __floats2bfloat162_rn(rz, rw);
    *(uint2*)ph = make_uint2(*(uint32_t*)&h0, *(uint32_t*)&h1);
    *(uint2*)pl = make_uint2(*(uint32_t*)&l0, *(uint32_t*)&l1);
}

// ---------------------------------------------------------------------------
// K0: recurrence coefficients
// ---------------------------------------------------------------------------
__global__ void k_coeff(const float* __restrict__ a_diag,
                        const float* __restrict__ g_diag,
                        const float* __restrict__ dt) {
    int s = threadIdx.x;
    float dts   = softplus_f(dt[s]) + 1e-4f;
    float omega = a_diag[s] * dts;
    float dec   = expf(-softplus_f(g_diag[s]) * dts);
    dec *= dec;
    float c = dec * cosf(omega);
    g_coeff[s] = c;
    float cl = c;
    #pragma unroll
    for (int i = 0; i < 8; i++) cl *= cl;   // c^256
    g_coeffL[s] = cl;
}

// ---------------------------------------------------------------------------
// K0b: pre-split the three weight matrices into bf16 hi/lo
// ---------------------------------------------------------------------------
__global__ void k_wsplit(const float* __restrict__ W0,
                         const float* __restrict__ W1,
                         const float* __restrict__ W2) {
    int id = blockIdx.x * 256 + threadIdx.x;      // grid 768
    int w = id >> 16, e = id & 65535;
    const float* src = (w == 0) ? W0 : (w == 1) ? W1 : W2;
    float v = src[e];
    __nv_bfloat16 h = __float2bfloat16_rn(v);
    g_whi[id] = h;
    g_wlo[id] = __float2bfloat16_rn(v - __bfloat162float(h));
}

// ---------------------------------------------------------------------------
// K1: LayerNorm per row (warp per row, 8 rows per block)
// ---------------------------------------------------------------------------
__global__ void k_ln(const float* __restrict__ x,
                     const float* __restrict__ w,
                     const float* __restrict__ b) {
    int row  = blockIdx.x * 8 + (threadIdx.x >> 5);
    int lane = threadIdx.x & 31;
    const float* xr = x + (size_t)row * H_;
    float v[8];
    float sum = 0.f;
    #pragma unroll
    for (int i = 0; i < 8; i++) { v[i] = xr[lane + 32 * i]; sum += v[i]; }
    #pragma unroll
    for (int o = 16; o; o >>= 1) sum += __shfl_xor_sync(0xffffffffu, sum, o);
    float mu = sum * (1.f / H_);
    float vs = 0.f;
    #pragma unroll
    for (int i = 0; i < 8; i++) { float d = v[i] - mu; vs += d * d; }
    #pragma unroll
    for (int o = 16; o; o >>= 1) vs += __shfl_xor_sync(0xffffffffu, vs, o);
    float rstd = rsqrtf(vs * (1.f / H_) + 1e-5f);
    float* outr = g_xn + (size_t)row * H_;
    #pragma unroll
    for (int i = 0; i < 8; i++) {
        int col = lane + 32 * i;
        outr[col] = (v[i] - mu) * rstd * w[col] + b[col];
    }
}

// ---------------------------------------------------------------------------
// bf16-split NT GEMM via mma.sync:  C[m,n] = sum_k A[m,k] * W[n,k]
// BM=128, BN=128 (grid.y=2), BK=32, 256 threads (8 warps 2m x 4n, tile 64x32).
// A fp32, split on the fly into double-buffered smem; W pre-split bf16,
// loaded via 3-stage cp.async. fp32 recovered as hh + hl + lh.
// Inner loop ordered term-major (hh over all nt, then hl, then lh) so no two
// consecutive MMAs share an accumulator -> no RAW stalls on the in-order warp.
// Per-accumulator op order is unchanged (hh,hl,lh) -> bitwise identical.
// EPI 0: C = acc                              (u)
// EPI 1: C = gelu(acc + p0[n]*p1[m,n])        (mixed)
// EPI 2: C = p0[m,n] + acc + p1[n]            (y)
// ---------------------------------------------------------------------------
#define ROWB 80
#define AHALF 10240             // 128 rows * 80B
#define ASTG  20480             // hi + lo
#define BSTG  20480
#define BBASE 40960             // after 2 A stages
#define SM_TOT (BBASE + 3 * BSTG)   // 102400 bytes

template <int EPI>
__global__ void __launch_bounds__(256, 2)
k_gemm_mma(const float* __restrict__ A,
           const __nv_bfloat16* __restrict__ Wh,
           const __nv_bfloat16* __restrict__ Wl,
           float* __restrict__ C,
           const float* __restrict__ p0,
           const float* __restrict__ p1) {
    extern __shared__ __align__(128) char sm[];
    uint32_t sb = smem_u32(sm);
    int tid = threadIdx.x, lane = tid & 31, wid = tid >> 5;
    int wm = wid >> 2, wn = wid & 3;        // 2 x 4 warp grid
    size_t mBase = (size_t)blockIdx.x * 128;
    int    nBase = blockIdx.y * 128;
    const float* Ab = A + mBase * 256;
    const __nv_bfloat16* Wbh = Wh + (size_t)nBase * 256;
    const __nv_bfloat16* Wbl = Wl + (size_t)nBase * 256;

    // A: 4 float4 per thread per chunk (128 rows x 32 cols fp32)
    // B: 2 hi + 2 lo cp.async-16B per thread per chunk (128 rows x 32 cols bf16)
    float4 ra[4];
    #pragma unroll
    for (int i = 0; i < 4; i++) {
        int idx = tid + 256 * i;
        ra[i] = *(const float4*)(Ab + (size_t)(idx >> 3) * 256 + ((idx & 7) << 2));
    }
    #pragma unroll
    for (int i = 0; i < 4; i++) {           // A chunk0 -> stage 0
        int idx = tid + 256 * i;
        int off = (idx >> 3) * ROWB + (idx & 7) * 8;
        split_store(ra[i], sm + off, sm + AHALF + off);
    }
    #pragma unroll
    for (int s = 0; s < 2; s++) {           // B chunks 0,1 -> stages 0,1
        uint32_t st = sb + BBASE + s * BSTG;
        int kt = s * 32;
        #pragma unroll
        for (int i = 0; i < 2; i++) {
            int slot = tid + 256 * i;
            int r = slot >> 2, q = slot & 3;
            uint32_t doff = r * ROWB + q * 16;
            cpa16(st + doff,         Wbh + (size_t)r * 256 + kt + q * 8);
            cpa16(st + AHALF + doff, Wbl + (size_t)r * 256 + kt + q * 8);
        }
        cpa_commit();
    }
    #pragma unroll
    for (int i = 0; i < 4; i++) {           // A chunk1 -> regs
        int idx = tid + 256 * i;
        ra[i] = *(const float4*)(Ab + (size_t)(idx >> 3) * 256 + 32 + ((idx & 7) << 2));
    }

    float acc[4][4][4];
    #pragma unroll
    for (int a = 0; a < 4; a++)
        #pragma unroll
        for (int b = 0; b < 4; b++)
            #pragma unroll
            for (int c = 0; c < 4; c++) acc[a][b][c] = 0.f;

    uint32_t aW = (uint32_t)((wm * 64 + (lane & 15)) * ROWB + ((lane >> 4) << 4));
    uint32_t bW = (uint32_t)((wn * 32 + (lane & 15)) * ROWB + ((lane >> 4) << 4));

    for (int ch = 0; ch < 8; ch++) {
        cpa_wait1();
        __syncthreads();

        if (ch + 2 < 8) {                   // B chunk ch+2 -> stage (ch+2)%3
            uint32_t st = sb + BBASE + ((ch + 2) % 3) * BSTG;
            int kt = (ch + 2) * 32;
            #pragma unroll
            for (int i = 0; i < 2; i++) {
                int slot = tid + 256 * i;
                int r = slot >> 2, q = slot & 3;
                uint32_t doff = r * ROWB + q * 16;
                cpa16(st + doff,         Wbh + (size_t)r * 256 + kt + q * 8);
                cpa16(st + AHALF + doff, Wbl + (size_t)r * 256 + kt + q * 8);
            }
        }
        cpa_commit();

        uint32_t aS = sb + (uint32_t)((ch & 1) * ASTG);
        uint32_t bS = sb + BBASE + (uint32_t)((ch % 3) * BSTG);
        uint32_t aAddr = aS + aW, bAddr = bS + bW;

        #pragma unroll
        for (int ks = 0; ks < 2; ks++) {
            uint32_t kO = ks * 32;
            uint32_t bh[8], bl[8];
            ldsm4(bh,     bAddr + kO);
            ldsm4(bh + 4, bAddr + 16 * ROWB + kO);
            ldsm4(bl,     bAddr + AHALF + kO);
            ldsm4(bl + 4, bAddr + AHALF + 16 * ROWB + kO);
            #pragma unroll
            for (int mt = 0; mt < 4; mt++) {
                uint32_t ah[4], al[4];
                ldsm4(ah, aAddr + mt * 16 * ROWB + kO);
                ldsm4(al, aAddr + AHALF + mt * 16 * ROWB + kO);
                // term-major: all 4 nt of hh, then hl, then lh.
                // consecutive MMAs never share an accumulator.
                #pragma unroll
                for (int nt = 0; nt < 4; nt++) {
                    int g = (nt >> 1) * 4, s2 = nt & 1;
                    mma16816(acc[mt][nt], ah, bh[g + s2], bh[g + s2 + 2]);
                }
                #pragma unroll
                for (int nt = 0; nt < 4; nt++) {
                    int g = (nt >> 1) * 4, s2 = nt & 1;
                    mma16816(acc[mt][nt], ah, bl[g + s2], bl[g + s2 + 2]);
                }
                #pragma unroll
                for (int nt = 0; nt < 4; nt++) {
                    int g = (nt >> 1) * 4, s2 = nt & 1;
                    mma16816(acc[mt][nt], al, bh[g + s2], bh[g + s2 + 2]);
                }
            }
            // Between ks0 and ks1: stage A(ch+1) into the other A buffer,
            // then prefetch A(ch+2) into registers.
            if (ks == 0 && ch < 7) {
                uint32_t aD = (uint32_t)(((ch + 1) & 1) * ASTG);
                #pragma unroll
                for (int i = 0; i < 4; i++) {
                    int idx = tid + 256 * i;
                    int off = (idx >> 3) * ROWB + (idx & 7) * 8;
                    split_store(ra[i], sm + aD + off, sm + aD + AHALF + off);
                }
                if (ch + 2 < 8) {
                    int kt = (ch + 2) * 32;
                    #pragma unroll
                    for (int i = 0; i < 4; i++) {
                        int idx = tid + 256 * i;
                        ra[i] = *(const float4*)(Ab + (size_t)(idx >> 3) * 256 + kt + ((idx & 7) << 2));
                    }
                }
            }
        }
    }

    // Epilogue: c0,c1 at (m, n..n+1); c2,c3 at (m+8, n..n+1)
    #pragma unroll
    for (int mt = 0; mt < 4; mt++) {
        size_t m0 = mBase + (size_t)(wm * 64 + mt * 16 + (lane >> 2));
        #pragma unroll
        for (int nt = 0; nt < 4; nt++) {
            int n = nBase + wn * 32 + nt * 8 + (lane & 3) * 2;
            #pragma unroll
            for (int h = 0; h < 2; h++) {
                size_t m = m0 + h * 8;
                size_t idx = m * 256 + (size_t)n;
                float v0 = acc[mt][nt][h * 2], v1 = acc[mt][nt][h * 2 + 1];
                float2 o;
                if (EPI == 0) {
                    o = make_float2(v0, v1);
                } else if (EPI == 1) {
                    o.x = gelu_tanh(v0 + p0[n]     * p1[idx]);
                    o.y = gelu_tanh(v1 + p0[n + 1] * p1[idx + 1]);
                } else {
                    o.x = p0[idx]     + v0 + p1[n];
                    o.y = p0[idx + 1] + v1 + p1[n + 1];
                }
                *(float2*)(C + idx) = o;
            }
        }
    }
}

// ---------------------------------------------------------------------------
// Scan phase 1: chunk-local scan (zero initial), in-place on g_u.
// ---------------------------------------------------------------------------
__global__ void k_scan1() {
    int s  = threadIdx.x;
    int ch = blockIdx.x;
    int b  = blockIdx.y;
    float c = g_coeff[s];
    size_t base = ((size_t)b * T_ + (size_t)ch * CHUNK) * S_ + s;
    float st = 0.f;
    #pragma unroll 8
    for (int t = 0; t < CHUNK; t++) {
        size_t idx = base + (size_t)t * S_;
        st = fmaf(c, st, g_u[idx]);
        g_u[idx] = st;
    }
    g_e[(b * NCH + ch) * S_ + s] = st;
}

// ---------------------------------------------------------------------------
// Scan phase 2: carry scan across chunks; writes carry_in + final_state.
// ---------------------------------------------------------------------------
__global__ void k_scan2(const float* __restrict__ state0, float* fs_out) {
    int s = threadIdx.x;
    int b = blockIdx.x;
    float cl  = g_coeffL[s];
    float Sin = state0[b * S_ + s];
    #pragma unroll
    for (int ch = 0; ch < NCH; ch++) {
        int e = (b * NCH + ch) * S_ + s;
        g_carry[e] = Sin;
        Sin = fmaf(cl, Sin, g_e[e]);
    }
    if (fs_out) fs_out[b * S_ + s] = Sin;
}

// ---------------------------------------------------------------------------
// Scan phase 3: correction  states[t] += coeff^(t+1) * carry_in
// ---------------------------------------------------------------------------
__global__ void k_scan3() {
    int s  = threadIdx.x;
    int ch = blockIdx.x;
    int b  = blockIdx.y;
    float c     = g_coeff[s];
    float carry = g_carry[(b * NCH + ch) * S_ + s];
    float cp = c;
    size_t base = ((size_t)b * T_ + (size_t)ch * CHUNK) * S_ + s;
    #pragma unroll 8
    for (int t = 0; t < CHUNK; t++) {
        size_t idx = base + (size_t)t * S_;
        g_u[idx] = fmaf(cp, carry, g_u[idx]);
        cp *= c;
    }
}

// ---------------------------------------------------------------------------
// Launch
// ---------------------------------------------------------------------------
extern "C" void kernel_launch(void* const* d_in, const int* in_sizes, int n_in,
                              void* d_out, int out_size) {
    const float* x      = (const float*)d_in[0];
    const float* state0 = (const float*)d_in[1];
    const float* Win    = (const float*)d_in[2];   // [S,H]
    const float* Wsh    = (const float*)d_in[3];   // [H,S]
    const float* direct = (const float*)d_in[4];   // [H]
    const float* a_diag = (const float*)d_in[5];
    const float* g_diag = (const float*)d_in[6];
    const float* dt     = (const float*)d_in[7];
    const float* nw     = (const float*)d_in[8];
    const float* nb     = (const float*)d_in[9];
    const float* ow     = (const float*)d_in[10];  // [H,H]
    const float* ob     = (const float*)d_in[11];
    float* out = (float*)d_out;

    float *xn, *u, *mx;
    __nv_bfloat16 *wh, *wl;
    cudaGetSymbolAddress((void**)&xn, g_xn);
    cudaGetSymbolAddress((void**)&u,  g_u);
    cudaGetSymbolAddress((void**)&mx, g_mx);
    cudaGetSymbolAddress((void**)&wh, g_whi);
    cudaGetSymbolAddress((void**)&wl, g_wlo);

    cudaFuncSetAttribute(k_gemm_mma<0>, cudaFuncAttributeMaxDynamicSharedMemorySize, SM_TOT);
    cudaFuncSetAttribute(k_gemm_mma<1>, cudaFuncAttributeMaxDynamicSharedMemorySize, SM_TOT);
    cudaFuncSetAttribute(k_gemm_mma<2>, cudaFuncAttributeMaxDynamicSharedMemorySize, SM_TOT);

    k_coeff<<<1, S_>>>(a_diag, g_diag, dt);
    k_wsplit<<<768, 256>>>(Win, Wsh, ow);
    k_ln<<<BT_ / 8, 256>>>(x, nw, nb);

    dim3 gg(BT_ / 128, 2);

    // u = xn @ Win^T
    k_gemm_mma<0><<<gg, 256, SM_TOT>>>(xn, wh, wl, u, nullptr, nullptr);

    // diagonal linear recurrence (chunked parallel scan)
    k_scan1<<<dim3(NCH, B_), 256>>>();
    float* fs_out = ((size_t)out_size >= (size_t)BT_ * H_ + (size_t)B_ * S_)
                        ? out + (size_t)BT_ * H_ : nullptr;
    k_scan2<<<B_, 256>>>(state0, fs_out);
    k_scan3<<<dim3(NCH, B_), 256>>>();

    // mixed = gelu(states @ Wsh^T + direct * xn)
    k_gemm_mma<1><<<gg, 256, SM_TOT>>>(u, wh + 65536, wl + 65536, mx, direct, xn);

    // y = x + mixed @ ow^T + ob
    k_gemm_mma<2><<<gg, 256, SM_TOT>>>(mx, wh + 131072, wl + 131072, out, x, ob);
}

// round 16
// speedup vs baseline: 1.5845x; 1.3459x over previous
#include <cuda_runtime.h>
#include <cuda_fp16.h>
#include <cstdint>

// Problem dimensions (fixed by the dataset)
#define B_   32
#define T_   4096
#define H_   256
#define S_   256
#define BT_  (B_ * T_)          // 131072 rows
#define CHUNK 256
#define NCH   (T_ / CHUNK)      // 16 chunks

// ---------------------------------------------------------------------------
// Scratch (static __device__ arrays — allocation-free per harness rules)
// ---------------------------------------------------------------------------
__device__ float g_xn[(size_t)BT_ * H_];   // layernormed x        [BT,H]
__device__ float g_u [(size_t)BT_ * S_];   // u = local (uncorrected) states
__device__ float g_mx[(size_t)BT_ * H_];   // gelu(mixed)          [BT,H]
__device__ float g_coeff [S_];
__device__ float g_coeffL[S_];
__device__ float g_pw    [CHUNK * S_];     // pw[p][s] = coeff[s]^(p+1)
__device__ float g_e     [B_ * NCH * S_];
__device__ float g_carry [B_ * NCH * S_];
__device__ __half g_wh[3 * H_ * H_];       // weights fp16 (Win,Wsh,ow)

// ---------------------------------------------------------------------------
// Math helpers
// ---------------------------------------------------------------------------
__device__ __forceinline__ float softplus_f(float v) {
    return fmaxf(v, 0.f) + log1pf(expf(-fabsf(v)));
}
__device__ __forceinline__ float gelu_tanh(float v) {
    float t = tanhf(0.7978845608028654f * (v + 0.044715f * v * v * v));
    return 0.5f * v * (1.0f + t);
}
__device__ __forceinline__ uint32_t smem_u32(const void* p) {
    uint32_t a;
    asm("{ .reg .u64 t; cvta.to.shared.u64 t, %1; cvt.u32.u64 %0, t; }"
        : "=r"(a) : "l"(p));
    return a;
}

// ---------------------------------------------------------------------------
// mma.sync / ldmatrix / cp.async helpers (base sm_80+ PTX)
// ---------------------------------------------------------------------------
__device__ __forceinline__ void ldsm4(uint32_t* r, uint32_t a) {
    asm volatile("ldmatrix.sync.aligned.m8n8.x4.shared.b16 {%0,%1,%2,%3}, [%4];"
                 : "=r"(r[0]), "=r"(r[1]), "=r"(r[2]), "=r"(r[3]) : "r"(a));
}
__device__ __forceinline__ void mma16816h(float* c, const uint32_t* a,
                                          uint32_t b0, uint32_t b1) {
    asm volatile(
        "mma.sync.aligned.m16n8k16.row.col.f32.f16.f16.f32 "
        "{%0,%1,%2,%3}, {%4,%5,%6,%7}, {%8,%9}, {%0,%1,%2,%3};"
        : "+f"(c[0]), "+f"(c[1]), "+f"(c[2]), "+f"(c[3])
        : "r"(a[0]), "r"(a[1]), "r"(a[2]), "r"(a[3]), "r"(b0), "r"(b1));
}
__device__ __forceinline__ void cpa16(uint32_t dst, const void* src) {
    asm volatile("cp.async.cg.shared.global [%0], [%1], 16;"
                 :: "r"(dst), "l"(src));
}
__device__ __forceinline__ void cpa_commit() {
    asm volatile("cp.async.commit_group;");
}
__device__ __forceinline__ void cpa_wait1() {
    asm volatile("cp.async.wait_group 1;");
}

// Convert float4 -> fp16 hi/lo pairs and store 8B each
__device__ __forceinline__ void split_storeh(float4 v, char* ph, char* pl) {
    __half2 h0 = __floats2half2_rn(v.x, v.y);
    __half2 h1 = __floats2half2_rn(v.z, v.w);
    float rx = v.x - __half2float(__low2half(h0));
    float ry = v.y - __half2float(__high2half(h0));
    float rz = v.z - __half2float(__low2half(h1));
    float rw = v.w - __half2float(__high2half(h1));
    __half2 l0 = __floats2half2_rn(rx, ry);
    __half2 l1 = __floats2half2_rn(rz, rw);
    *(uint2*)ph = make_uint2(*(uint32_t*)&h0, *(uint32_t*)&h1);
    *(uint2*)pl = make_uint2(*(uint32_t*)&l0, *(uint32_t*)&l1);
}

// ---------------------------------------------------------------------------
// K0: recurrence coefficients + per-chunk power table pw[p][s]=c^(p+1)
// (iterative product — identical value sequence to the old scan3 loop)
// ---------------------------------------------------------------------------
__global__ void k_coeff(const float* __restrict__ a_diag,
                        const float* __restrict__ g_diag,
                        const float* __restrict__ dt) {
    int s = threadIdx.x;
    float dts   = softplus_f(dt[s]) + 1e-4f;
    float omega = a_diag[s] * dts;
    float dec   = expf(-softplus_f(g_diag[s]) * dts);
    dec *= dec;
    float c = dec * cosf(omega);
    g_coeff[s] = c;
    float cp = c;
    for (int p = 0; p < CHUNK; p++) {
        g_pw[p * S_ + s] = cp;
        cp *= c;
    }
    float cl = c;
    #pragma unroll
    for (int i = 0; i < 8; i++) cl *= cl;   // c^256
    g_coeffL[s] = cl;
}

// ---------------------------------------------------------------------------
// K0b: round the three weight matrices to fp16
// ---------------------------------------------------------------------------
__global__ void k_wsplit(const float* __restrict__ W0,
                         const float* __restrict__ W1,
                         const float* __restrict__ W2) {
    int id = blockIdx.x * 256 + threadIdx.x;      // grid 768
    int w = id >> 16, e = id & 65535;
    const float* src = (w == 0) ? W0 : (w == 1) ? W1 : W2;
    g_wh[id] = __float2half_rn(src[e]);
}

// ---------------------------------------------------------------------------
// K1: LayerNorm per row (warp per row, 8 rows per block)
// ---------------------------------------------------------------------------
__global__ void k_ln(const float* __restrict__ x,
                     const float* __restrict__ w,
                     const float* __restrict__ b) {
    int row  = blockIdx.x * 8 + (threadIdx.x >> 5);
    int lane = threadIdx.x & 31;
    const float* xr = x + (size_t)row * H_;
    float v[8];
    float sum = 0.f;
    #pragma unroll
    for (int i = 0; i < 8; i++) { v[i] = xr[lane + 32 * i]; sum += v[i]; }
    #pragma unroll
    for (int o = 16; o; o >>= 1) sum += __shfl_xor_sync(0xffffffffu, sum, o);
    float mu = sum * (1.f / H_);
    float vs = 0.f;
    #pragma unroll
    for (int i = 0; i < 8; i++) { float d = v[i] - mu; vs += d * d; }
    #pragma unroll
    for (int o = 16; o; o >>= 1) vs += __shfl_xor_sync(0xffffffffu, vs, o);
    float rstd = rsqrtf(vs * (1.f / H_) + 1e-5f);
    float* outr = g_xn + (size_t)row * H_;
    #pragma unroll
    for (int i = 0; i < 8; i++) {
        int col = lane + 32 * i;
        outr[col] = (v[i] - mu) * rstd * w[col] + b[col];
    }
}

// ---------------------------------------------------------------------------
// fp16 2-term split NT GEMM via mma.sync:  C[m,n] = sum_k A[m,k] * W[n,k]
// BM=128, BN=128 (grid.y=2), BK=32, 256 threads (8 warps 2m x 4n, tile 64x32).
// A fp32 split on the fly into fp16 hi/lo (double-buffered smem);
// W pre-rounded fp16 (single term), 3-stage cp.async.
// D = A_hi*W + A_lo*W   (W fp16 rounding error ~1e-4 relative, only source).
// CORR (EPI==1): A-load applies the scan carry correction
//   a = fmaf(pw[t%256][s], carry[b][t/256][s], u[row][s])   (== old scan3)
// EPI 0: C = acc                              (u)
// EPI 1: C = gelu(acc + p0[n]*p1[m,n])        (mixed)
// EPI 2: C = p0[m,n] + acc + p1[n]            (y)
// ---------------------------------------------------------------------------
#define ROWB 80
#define AHALF 10240             // 128 rows * 80B
#define ASTG  20480             // hi + lo
#define BSTG  10240             // hi only
#define BBASE 40960             // after 2 A stages
#define SM_TOT (BBASE + 3 * BSTG)   // 71680 bytes

template <int EPI>
__device__ __forceinline__ float4 loadA(const float* __restrict__ Ab,
                                        size_t mBase, int r, int k,
                                        const float* __restrict__ PW,
                                        const float* __restrict__ CAR) {
    float4 v = *(const float4*)(Ab + (size_t)r * 256 + k);
    if (EPI == 1) {
        size_t row = mBase + (size_t)r;        // = b*4096 + ch*256 + p
        int p  = (int)(row & 255);
        int bc = (int)(row >> 8);              // b*16 + ch
        float4 w  = *(const float4*)(PW + p * 256 + k);
        float4 cr = *(const float4*)(CAR + (size_t)bc * 256 + k);
        v.x = fmaf(w.x, cr.x, v.x);
        v.y = fmaf(w.y, cr.y, v.y);
        v.z = fmaf(w.z, cr.z, v.z);
        v.w = fmaf(w.w, cr.w, v.w);
    }
    return v;
}

template <int EPI>
__global__ void __launch_bounds__(256, 2)
k_gemm_mma(const float* __restrict__ A,
           const __half* __restrict__ Wh,
           float* __restrict__ C,
           const float* __restrict__ p0,
           const float* __restrict__ p1,
           const float* __restrict__ PW,
           const float* __restrict__ CAR) {
    extern __shared__ __align__(128) char sm[];
    uint32_t sb = smem_u32(sm);
    int tid = threadIdx.x, lane = tid & 31, wid = tid >> 5;
    int wm = wid >> 2, wn = wid & 3;        // 2 x 4 warp grid
    size_t mBase = (size_t)blockIdx.x * 128;
    int    nBase = blockIdx.y * 128;
    const float* Ab = A + mBase * 256;
    const __half* Wbh = Wh + (size_t)nBase * 256;

    // A: 4 float4 per thread per chunk (128 rows x 32 cols fp32)
    // B: 2 cp.async-16B per thread per chunk (128 rows x 32 cols fp16)
    float4 ra[4];
    #pragma unroll
    for (int i = 0; i < 4; i++) {
        int idx = tid + 256 * i;
        ra[i] = loadA<EPI>(Ab, mBase, idx >> 3, (idx & 7) << 2, PW, CAR);
    }
    #pragma unroll
    for (int i = 0; i < 4; i++) {           // A chunk0 -> stage 0
        int idx = tid + 256 * i;
        int off = (idx >> 3) * ROWB + (idx & 7) * 8;
        split_storeh(ra[i], sm + off, sm + AHALF + off);
    }
    #pragma unroll
    for (int s = 0; s < 2; s++) {           // B chunks 0,1 -> stages 0,1
        uint32_t st = sb + BBASE + s * BSTG;
        int kt = s * 32;
        #pragma unroll
        for (int i = 0; i < 2; i++) {
            int slot = tid + 256 * i;
            int r = slot >> 2, q = slot & 3;
            cpa16(st + r * ROWB + q * 16, Wbh + (size_t)r * 256 + kt + q * 8);
        }
        cpa_commit();
    }
    #pragma unroll
    for (int i = 0; i < 4; i++) {           // A chunk1 -> regs
        int idx = tid + 256 * i;
        ra[i] = loadA<EPI>(Ab, mBase, idx >> 3, 32 + ((idx & 7) << 2), PW, CAR);
    }

    float acc[4][4][4];
    #pragma unroll
    for (int a = 0; a < 4; a++)
        #pragma unroll
        for (int b = 0; b < 4; b++)
            #pragma unroll
            for (int c = 0; c < 4; c++) acc[a][b][c] = 0.f;

    uint32_t aW = (uint32_t)((wm * 64 + (lane & 15)) * ROWB + ((lane >> 4) << 4));
    uint32_t bW = (uint32_t)((wn * 32 + (lane & 15)) * ROWB + ((lane >> 4) << 4));

    for (int ch = 0; ch < 8; ch++) {
        cpa_wait1();
        __syncthreads();

        if (ch + 2 < 8) {                   // B chunk ch+2 -> stage (ch+2)%3
            uint32_t st = sb + BBASE + ((ch + 2) % 3) * BSTG;
            int kt = (ch + 2) * 32;
            #pragma unroll
            for (int i = 0; i < 2; i++) {
                int slot = tid + 256 * i;
                int r = slot >> 2, q = slot & 3;
                cpa16(st + r * ROWB + q * 16, Wbh + (size_t)r * 256 + kt + q * 8);
            }
        }
        cpa_commit();

        uint32_t aS = sb + (uint32_t)((ch & 1) * ASTG);
        uint32_t bS = sb + BBASE + (uint32_t)((ch % 3) * BSTG);
        uint32_t aAddr = aS + aW, bAddr = bS + bW;

        #pragma unroll
        for (int ks = 0; ks < 2; ks++) {
            uint32_t kO = ks * 32;
            uint32_t bh[8];
            ldsm4(bh,     bAddr + kO);
            ldsm4(bh + 4, bAddr + 16 * ROWB + kO);
            #pragma unroll
            for (int mt = 0; mt < 4; mt++) {
                uint32_t ah[4], al[4];
                ldsm4(ah, aAddr + mt * 16 * ROWB + kO);
                ldsm4(al, aAddr + AHALF + mt * 16 * ROWB + kO);
                // term-major: hi over all nt, then lo over all nt.
                #pragma unroll
                for (int nt = 0; nt < 4; nt++) {
                    int g = (nt >> 1) * 4, s2 = nt & 1;
                    mma16816h(acc[mt][nt], ah, bh[g + s2], bh[g + s2 + 2]);
                }
                #pragma unroll
                for (int nt = 0; nt < 4; nt++) {
                    int g = (nt >> 1) * 4, s2 = nt & 1;
                    mma16816h(acc[mt][nt], al, bh[g + s2], bh[g + s2 + 2]);
                }
            }
            // Between ks0 and ks1: stage A(ch+1) into the other A buffer,
            // then prefetch A(ch+2) into registers.
            if (ks == 0 && ch < 7) {
                uint32_t aD = (uint32_t)(((ch + 1) & 1) * ASTG);
                #pragma unroll
                for (int i = 0; i < 4; i++) {
                    int idx = tid + 256 * i;
                    int off = (idx >> 3) * ROWB + (idx & 7) * 8;
                    split_storeh(ra[i], sm + aD + off, sm + aD + AHALF + off);
                }
                if (ch + 2 < 8) {
                    int kt = (ch + 2) * 32;
                    #pragma unroll
                    for (int i = 0; i < 4; i++) {
                        int idx = tid + 256 * i;
                        ra[i] = loadA<EPI>(Ab, mBase, idx >> 3,
                                           kt + ((idx & 7) << 2), PW, CAR);
                    }
                }
            }
        }
    }

    // Epilogue: c0,c1 at (m, n..n+1); c2,c3 at (m+8, n..n+1)
    #pragma unroll
    for (int mt = 0; mt < 4; mt++) {
        size_t m0 = mBase + (size_t)(wm * 64 + mt * 16 + (lane >> 2));
        #pragma unroll
        for (int nt = 0; nt < 4; nt++) {
            int n = nBase + wn * 32 + nt * 8 + (lane & 3) * 2;
            #pragma unroll
            for (int h = 0; h < 2; h++) {
                size_t m = m0 + h * 8;
                size_t idx = m * 256 + (size_t)n;
                float v0 = acc[mt][nt][h * 2], v1 = acc[mt][nt][h * 2 + 1];
                float2 o;
                if (EPI == 0) {
                    o = make_float2(v0, v1);
                } else if (EPI == 1) {
                    o.x = gelu_tanh(v0 + p0[n]     * p1[idx]);
                    o.y = gelu_tanh(v1 + p0[n + 1] * p1[idx + 1]);
                } else {
                    o.x = p0[idx]     + v0 + p1[n];
                    o.y = p0[idx + 1] + v1 + p1[n + 1];
                }
                *(float2*)(C + idx) = o;
            }
        }
    }
}

// ---------------------------------------------------------------------------
// Scan phase 1: chunk-local scan (zero initial), in-place on g_u.
// ---------------------------------------------------------------------------
__global__ void k_scan1() {
    int s  = threadIdx.x;
    int ch = blockIdx.x;
    int b  = blockIdx.y;
    float c = g_coeff[s];
    size_t base = ((size_t)b * T_ + (size_t)ch * CHUNK) * S_ + s;
    float st = 0.f;
    #pragma unroll 8
    for (int t = 0; t < CHUNK; t++) {
        size_t idx = base + (size_t)t * S_;
        st = fmaf(c, st, g_u[idx]);
        g_u[idx] = st;
    }
    g_e[(b * NCH + ch) * S_ + s] = st;
}

// ---------------------------------------------------------------------------
// Scan phase 2: carry scan across chunks; writes carry_in + final_state.
// ---------------------------------------------------------------------------
__global__ void k_scan2(const float* __restrict__ state0, float* fs_out) {
    int s = threadIdx.x;
    int b = blockIdx.x;
    float cl  = g_coeffL[s];
    float Sin = state0[b * S_ + s];
    #pragma unroll
    for (int ch = 0; ch < NCH; ch++) {
        int e = (b * NCH + ch) * S_ + s;
        g_carry[e] = Sin;
        Sin = fmaf(cl, Sin, g_e[e]);
    }
    if (fs_out) fs_out[b * S_ + s] = Sin;
}

// ---------------------------------------------------------------------------
// Launch
// ---------------------------------------------------------------------------
extern "C" void kernel_launch(void* const* d_in, const int* in_sizes, int n_in,
                              void* d_out, int out_size) {
    const float* x      = (const float*)d_in[0];
    const float* state0 = (const float*)d_in[1];
    const float* Win    = (const float*)d_in[2];   // [S,H]
    const float* Wsh    = (const float*)d_in[3];   // [H,S]
    const float* direct = (const float*)d_in[4];   // [H]
    const float* a_diag = (const float*)d_in[5];
    const float* g_diag = (const float*)d_in[6];
    const float* dt     = (const float*)d_in[7];
    const float* nw     = (const float*)d_in[8];
    const float* nb     = (const float*)d_in[9];
    const float* ow     = (const float*)d_in[10];  // [H,H]
    const float* ob     = (const float*)d_in[11];
    float* out = (float*)d_out;

    float *xn, *u, *mx, *pw, *car;
    __half *wh;
    cudaGetSymbolAddress((void**)&xn,  g_xn);
    cudaGetSymbolAddress((void**)&u,   g_u);
    cudaGetSymbolAddress((void**)&mx,  g_mx);
    cudaGetSymbolAddress((void**)&pw,  g_pw);
    cudaGetSymbolAddress((void**)&car, g_carry);
    cudaGetSymbolAddress((void**)&wh,  g_wh);

    cudaFuncSetAttribute(k_gemm_mma<0>, cudaFuncAttributeMaxDynamicSharedMemorySize, SM_TOT);
    cudaFuncSetAttribute(k_gemm_mma<1>, cudaFuncAttributeMaxDynamicSharedMemorySize, SM_TOT);
    cudaFuncSetAttribute(k_gemm_mma<2>, cudaFuncAttributeMaxDynamicSharedMemorySize, SM_TOT);

    k_coeff<<<1, S_>>>(a_diag, g_diag, dt);
    k_wsplit<<<768, 256>>>(Win, Wsh, ow);
    k_ln<<<BT_ / 8, 256>>>(x, nw, nb);

    dim3 gg(BT_ / 128, 2);

    // u = xn @ Win^T
    k_gemm_mma<0><<<gg, 256, SM_TOT>>>(xn, wh, u, nullptr, nullptr,
                                       nullptr, nullptr);

    // diagonal linear recurrence (chunked parallel scan; correction fused
    // into GEMM<1>'s A path)
    k_scan1<<<dim3(NCH, B_), 256>>>();
    float* fs_out = ((size_t)out_size >= (size_t)BT_ * H_ + (size_t)B_ * S_)
                        ? out + (size_t)BT_ * H_ : nullptr;
    k_scan2<<<B_, 256>>>(state0, fs_out);

    // mixed = gelu((states_corrected) @ Wsh^T + direct * xn)
    k_gemm_mma<1><<<gg, 256, SM_TOT>>>(u, wh + 65536, mx, direct, xn,
                                       pw, car);

    // y = x + mixed @ ow^T + ob
    k_gemm_mma<2><<<gg, 256, SM_TOT>>>(mx, wh + 131072, out, x, ob,
                                       nullptr, nullptr);
}